// round 11
// baseline (speedup 1.0000x reference)
#include <cuda_runtime.h>
#include <cuda_bf16.h>

// out[k] = tfa_dist(X[ids[2k]], X[ids[2k+1]]), k=0..99, D=64.
//   d2 = ||xi||^2 + ||xj||^2 - 2*dot(xi,xj);  d = d2 > 0 ? sqrt(d2) : 0.
//
// Single CTA, 800 threads, 8 threads per pair. Each thread loads 2 float4s
// per row (4 independent LDG.128 issued before any math, MLP=4; 8 lanes x
// 32B = 256B per row, fully coalesced). 3-step butterfly reduce within the
// 8-lane group; group-lane 0 writes. One block => minimal grid teardown.

#define CARD 50
#define NPAIRS (2 * CARD)   // 100 output distances
#define DIMS 64
#define TPP 8               // threads per pair

__global__ void __launch_bounds__(NPAIRS * TPP, 1)
rips_pairs_kernel(const float* __restrict__ X,
                  const int* __restrict__ ids,
                  float* __restrict__ out) {
    int tid  = threadIdx.x;
    int pair = tid >> 3;          // one pair per 8 threads
    int gl   = tid & 7;           // lane within 8-lane group

    // Both indices in one LDG.64.
    int2 ij = __ldg(reinterpret_cast<const int2*>(ids) + pair);

    const float4* rowi = reinterpret_cast<const float4*>(X + (long)ij.x * DIMS);
    const float4* rowj = reinterpret_cast<const float4*>(X + (long)ij.y * DIMS);

    // 4 independent loads issued before any math: one DRAM/L2 round trip.
    float4 a0 = __ldg(&rowi[gl]);
    float4 a1 = __ldg(&rowi[gl + 8]);
    float4 b0 = __ldg(&rowj[gl]);
    float4 b1 = __ldg(&rowj[gl + 8]);

    float si  = a0.x * a0.x + a0.y * a0.y + a0.z * a0.z + a0.w * a0.w
              + a1.x * a1.x + a1.y * a1.y + a1.z * a1.z + a1.w * a1.w;
    float sj  = b0.x * b0.x + b0.y * b0.y + b0.z * b0.z + b0.w * b0.w
              + b1.x * b1.x + b1.y * b1.y + b1.z * b1.z + b1.w * b1.w;
    float dot = a0.x * b0.x + a0.y * b0.y + a0.z * b0.z + a0.w * b0.w
              + a1.x * b1.x + a1.y * b1.y + a1.z * b1.z + a1.w * b1.w;

    // Butterfly reduce within the 8-lane group.
    #pragma unroll
    for (int off = 4; off > 0; off >>= 1) {
        si  += __shfl_xor_sync(0xFFFFFFFFu, si,  off);
        sj  += __shfl_xor_sync(0xFFFFFFFFu, sj,  off);
        dot += __shfl_xor_sync(0xFFFFFFFFu, dot, off);
    }

    if (gl == 0) {
        float d2 = si + sj - 2.0f * dot;
        out[pair] = (d2 > 0.0f) ? sqrtf(d2) : 0.0f;
    }
}

extern "C" void kernel_launch(void* const* d_in, const int* in_sizes, int n_in,
                              void* d_out, int out_size) {
    const float* X   = (const float*)d_in[0];   // [8192, 64] float32
    const int*   ids = (const int*)d_in[1];     // [200] int32
    float*       out = (float*)d_out;           // [50, 2] = 100 floats

    // 100 pairs * 8 threads = 800 threads, one block.
    rips_pairs_kernel<<<1, NPAIRS * TPP>>>(X, ids, out);
}